// round 16
// baseline (speedup 1.0000x reference)
#include <cuda_runtime.h>
#include <math.h>

// Problem constants
#define Bn   4
#define Tn   4096
#define Dn   1024
#define Hn   16
#define HD   64
#define BH   64            // Bn*Hn
#define NCH  32            // Tn/128
#define Mn   16384         // Bn*Tn

// Scratch (device globals; no allocations allowed)
static __device__ float    g_q[(size_t)BH * Tn * HD];   // roped Q, [bh, t, 64]
static __device__ float    g_k[(size_t)BH * Tn * HD];   // roped K
static __device__ float    g_v[(size_t)BH * Tn * HD];   // V
static __device__ float    g_xo[(size_t)Mn * Dn];       // unsorted attn output
static __device__ unsigned g_keys[BH * Tn];             // (bucket<<12)|t
static __device__ int      g_sidx[BH * Tn];             // sorted_idx per (bh)
static __device__ int      g_flags[2];                  // [0]=qkv bad, [1]=proj bad

__global__ void clear_flags_kernel() { g_flags[0] = 0; g_flags[1] = 0; }

// ---------------------------------------------------------------------------
// Double-buffered FFMA GEMM. Round-0's EXACT per-thread index math and inner
// compute (bit-identical FMA order, k ascending) — only additions are the
// ping-pong buffer and single sync per chunk with register prefetch.
// qkv_scatter=1: A=x, W=W_attn (N=3072) -> scatter q/k/v head layout.
// qkv_scatter=0: C row-major (output projection).
// ---------------------------------------------------------------------------
__global__ __launch_bounds__(256) void gemm_db_kernel(
    const float* __restrict__ A, const float* __restrict__ W,
    const float* __restrict__ bias, float* __restrict__ C,
    int N_total, int qkv_scatter)
{
    __shared__ float As[2][8][128];
    __shared__ float Bs[2][8][128];

    int tid = threadIdx.x;
    int bm = blockIdx.y * 128;
    int bn = blockIdx.x * 128;
    int arow = tid >> 1,  acol = (tid & 1) << 2;     // round-0 decomposition
    int brow = tid >> 5,  bcol = (tid & 31) << 2;
    const float* Ap = A + (size_t)(bm + arow) * 1024 + acol;
    const float* Bp = W + (size_t)brow * N_total + bn + bcol;
    int ty = tid >> 4, tx = tid & 15;

    float acc[8][8];
#pragma unroll
    for (int i = 0; i < 8; i++)
#pragma unroll
        for (int j = 0; j < 8; j++) acc[i][j] = 0.f;

    // Prologue: chunk 0 -> buffer 0 (round-0 store pattern)
    {
        float4 a4 = *(const float4*)Ap;
        float4 b4 = *(const float4*)Bp;
        Ap += 8;
        Bp += (size_t)8 * N_total;
        As[0][acol + 0][arow] = a4.x;
        As[0][acol + 1][arow] = a4.y;
        As[0][acol + 2][arow] = a4.z;
        As[0][acol + 3][arow] = a4.w;
        *(float4*)&Bs[0][brow][bcol] = b4;
    }
    __syncthreads();

    for (int c = 0; c < 128; c++) {                  // 128 chunks of BK=8
        int cur = c & 1;

        // Register prefetch of chunk c+1 (hides LDG latency behind compute)
        float4 a4n, b4n;
        if (c < 127) {
            a4n = *(const float4*)Ap;
            b4n = *(const float4*)Bp;
            Ap += 8;
            Bp += (size_t)8 * N_total;
        }

        // Compute: round-0's exact inner loop from the current buffer
#pragma unroll
        for (int kk = 0; kk < 8; kk++) {
            float a[8], b[8];
            *(float4*)&a[0] = *(const float4*)&As[cur][kk][ty * 8];
            *(float4*)&a[4] = *(const float4*)&As[cur][kk][ty * 8 + 4];
            *(float4*)&b[0] = *(const float4*)&Bs[cur][kk][tx * 8];
            *(float4*)&b[4] = *(const float4*)&Bs[cur][kk][tx * 8 + 4];
#pragma unroll
            for (int i = 0; i < 8; i++)
#pragma unroll
                for (int j = 0; j < 8; j++) acc[i][j] += a[i] * b[j];
        }

        // Store prefetched chunk into the spare buffer
        if (c < 127) {
            int nxt = cur ^ 1;
            As[nxt][acol + 0][arow] = a4n.x;
            As[nxt][acol + 1][arow] = a4n.y;
            As[nxt][acol + 2][arow] = a4n.z;
            As[nxt][acol + 3][arow] = a4n.w;
            *(float4*)&Bs[nxt][brow][bcol] = b4n;
        }
        __syncthreads();
    }

    // Epilogue (round-0's)
    int n0 = bn + tx * 8;
    float bb[8];
#pragma unroll
    for (int j = 0; j < 8; j++) bb[j] = bias[n0 + j];

    if (qkv_scatter) {
        int which = n0 >> 10;                        // 0=q, 1=k, 2=v
        float* dst = (which == 0) ? g_q : (which == 1 ? g_k : g_v);
        int h = (n0 & 1023) >> 6, j0 = n0 & 63;
#pragma unroll
        for (int i = 0; i < 8; i++) {
            int m = bm + ty * 8 + i;
            int b = m >> 12, t = m & 4095;
            float* row = dst + (((size_t)(b * Hn + h) * Tn) + t) * HD + j0;
#pragma unroll
            for (int j = 0; j < 8; j++) row[j] = acc[i][j] + bb[j];
        }
    } else {
#pragma unroll
        for (int i = 0; i < 8; i++) {
            int m = bm + ty * 8 + i;
            float* row = C + (size_t)m * N_total + n0;
#pragma unroll
            for (int j = 0; j < 8; j++) row[j] = acc[i][j] + bb[j];
        }
    }
}

// ---------------------------------------------------------------------------
// Check kernels: 1 warp per 128x128 output tile verifies 32 elements with a
// coalesced W-column dot. Covers the Q region too.
// ---------------------------------------------------------------------------
__global__ __launch_bounds__(256) void check_qkv_kernel(
    const float* __restrict__ x, const float* __restrict__ W,
    const float* __restrict__ bias)
{
    int w = (blockIdx.x * blockDim.x + threadIdx.x) >> 5;
    int lane = threadIdx.x & 31;
    if (w >= 128 * 24) return;
    int ty = w / 24, tx = w % 24;
    int m  = ty * 128 + ((ty * 7 + tx * 3) & 127);
    int n  = tx * 128 + ((ty * 29 + tx * 13) & 96) + lane;
    float acc = bias[n];
    const float* xr = &x[(size_t)m * 1024];
    for (int k = 0; k < 1024; k++)
        acc += xr[k] * W[(size_t)k * 3072 + n];
    int which = n >> 10;
    const float* dst = (which == 0) ? g_q : (which == 1 ? g_k : g_v);
    int h = (n & 1023) >> 6, j0 = n & 63, b = m >> 12, t = m & 4095;
    float got = dst[(((size_t)(b * Hn + h) * Tn) + t) * HD + j0];
    float diff = fabsf(got - acc);
    if (!(diff <= 3e-3f * (1.0f + fabsf(acc)))) atomicExch(&g_flags[0], 1);
}

__global__ __launch_bounds__(256) void check_proj_kernel(
    const float* __restrict__ W, const float* __restrict__ bias,
    const float* __restrict__ out)
{
    int w = (blockIdx.x * blockDim.x + threadIdx.x) >> 5;
    int lane = threadIdx.x & 31;
    if (w >= 128 * 8) return;
    int ty = w >> 3, tx = w & 7;
    int m  = ty * 128 + ((ty * 7 + tx * 3) & 127);
    int n  = tx * 128 + ((ty * 29 + tx * 13) & 96) + lane;
    float acc = bias[n];
    const float* xr = &g_xo[(size_t)m * 1024];
    for (int k = 0; k < 1024; k++)
        acc += xr[k] * W[(size_t)k * 1024 + n];
    float got = out[(size_t)m * 1024 + n];
    float diff = fabsf(got - acc);
    if (!(diff <= 3e-3f * (1.0f + fabsf(acc)))) atomicExch(&g_flags[1], 1);
}

// ---------------------------------------------------------------------------
// Guard GEMMs: round-0's proven kernel (bit-identical numerics), flag-gated.
// ---------------------------------------------------------------------------
__global__ __launch_bounds__(256) void guard_qkv_kernel(
    const float* __restrict__ X, const float* __restrict__ W,
    const float* __restrict__ bias)
{
    if (*(volatile int*)&g_flags[0] == 0) return;
    const int K = Dn, N = 3 * Dn;
    __shared__ float As[8][128];
    __shared__ float Bs[8][128];
    int tid = threadIdx.x;
    int bm = blockIdx.y * 128;
    int bn = blockIdx.x * 128;
    int arow = tid >> 1,  acol = (tid & 1) << 2;
    int brow = tid >> 5,  bcol = (tid & 31) << 2;
    const float* Ap = X + (size_t)(bm + arow) * K + acol;
    const float* Bp = W + (size_t)brow * N + bn + bcol;
    int ty = tid >> 4, tx = tid & 15;
    float acc[8][8];
#pragma unroll
    for (int i = 0; i < 8; i++)
#pragma unroll
        for (int j = 0; j < 8; j++) acc[i][j] = 0.f;
    for (int k0 = 0; k0 < K; k0 += 8) {
        float4 a4 = *(const float4*)Ap;
        float4 b4 = *(const float4*)Bp;
        As[acol + 0][arow] = a4.x;
        As[acol + 1][arow] = a4.y;
        As[acol + 2][arow] = a4.z;
        As[acol + 3][arow] = a4.w;
        *(float4*)&Bs[brow][bcol] = b4;
        __syncthreads();
#pragma unroll
        for (int kk = 0; kk < 8; kk++) {
            float a[8], b[8];
            *(float4*)&a[0] = *(const float4*)&As[kk][ty * 8];
            *(float4*)&a[4] = *(const float4*)&As[kk][ty * 8 + 4];
            *(float4*)&b[0] = *(const float4*)&Bs[kk][tx * 8];
            *(float4*)&b[4] = *(const float4*)&Bs[kk][tx * 8 + 4];
#pragma unroll
            for (int i = 0; i < 8; i++)
#pragma unroll
                for (int j = 0; j < 8; j++) acc[i][j] += a[i] * b[j];
        }
        __syncthreads();
        Ap += 8;
        Bp += (size_t)8 * N;
    }
    int n0 = bn + tx * 8;
    int which = n0 >> 10;
    float* dst = (which == 0) ? g_q : (which == 1 ? g_k : g_v);
    int h = (n0 & 1023) >> 6, j0 = n0 & 63;
    float bb[8];
#pragma unroll
    for (int j = 0; j < 8; j++) bb[j] = bias[n0 + j];
#pragma unroll
    for (int i = 0; i < 8; i++) {
        int m = bm + ty * 8 + i;
        int b = m >> 12, t = m & 4095;
        float* row = dst + (((size_t)(b * Hn + h) * Tn) + t) * HD + j0;
#pragma unroll
        for (int j = 0; j < 8; j++) row[j] = acc[i][j] + bb[j];
    }
}

__global__ __launch_bounds__(256) void guard_proj_kernel(
    const float* __restrict__ W, const float* __restrict__ bias,
    float* __restrict__ C)
{
    if (*(volatile int*)&g_flags[1] == 0) return;
    const int K = Dn, N = Dn;
    __shared__ float As[8][128];
    __shared__ float Bs[8][128];
    int tid = threadIdx.x;
    int bm = blockIdx.y * 128;
    int bn = blockIdx.x * 128;
    int arow = tid >> 1,  acol = (tid & 1) << 2;
    int brow = tid >> 5,  bcol = (tid & 31) << 2;
    const float* Ap = g_xo + (size_t)(bm + arow) * K + acol;
    const float* Bp = W + (size_t)brow * N + bn + bcol;
    int ty = tid >> 4, tx = tid & 15;
    float acc[8][8];
#pragma unroll
    for (int i = 0; i < 8; i++)
#pragma unroll
        for (int j = 0; j < 8; j++) acc[i][j] = 0.f;
    for (int k0 = 0; k0 < K; k0 += 8) {
        float4 a4 = *(const float4*)Ap;
        float4 b4 = *(const float4*)Bp;
        As[acol + 0][arow] = a4.x;
        As[acol + 1][arow] = a4.y;
        As[acol + 2][arow] = a4.z;
        As[acol + 3][arow] = a4.w;
        *(float4*)&Bs[brow][bcol] = b4;
        __syncthreads();
#pragma unroll
        for (int kk = 0; kk < 8; kk++) {
            float a[8], b[8];
            *(float4*)&a[0] = *(const float4*)&As[kk][ty * 8];
            *(float4*)&a[4] = *(const float4*)&As[kk][ty * 8 + 4];
            *(float4*)&b[0] = *(const float4*)&Bs[kk][tx * 8];
            *(float4*)&b[4] = *(const float4*)&Bs[kk][tx * 8 + 4];
#pragma unroll
            for (int i = 0; i < 8; i++)
#pragma unroll
                for (int j = 0; j < 8; j++) acc[i][j] += a[i] * b[j];
        }
        __syncthreads();
        Ap += 8;
        Bp += (size_t)8 * N;
    }
    float bb[8];
#pragma unroll
    for (int j = 0; j < 8; j++) bb[j] = bias[bn + tx * 8 + j];
#pragma unroll
    for (int i = 0; i < 8; i++) {
        int m = bm + ty * 8 + i;
        float* row = C + (size_t)m * N + bn + tx * 8;
#pragma unroll
        for (int j = 0; j < 8; j++) row[j] = acc[i][j] + bb[j];
    }
}

// ---------------------------------------------------------------------------
// RoPE on q and k in-place (matches JAX interleaved-rotate semantics).
// ---------------------------------------------------------------------------
__global__ void rope_kernel()
{
    int idx = blockIdx.x * blockDim.x + threadIdx.x;
    if (idx >= BH * Tn * 32) return;
    int p  = idx & 31;
    int rt = idx >> 5;
    int t  = rt & 4095;
    int d0 = p * 2, d1 = p * 2 + 1;
    float e0 = (float)(d0 & 31) * (1.0f / 32.0f);
    float e1 = (float)(d1 & 31) * (1.0f / 32.0f);
    float inv0 = 1.0f / powf(10000.0f, e0);
    float inv1 = 1.0f / powf(10000.0f, e1);
    float a0 = (float)t * inv0, a1 = (float)t * inv1;
    float s0, c0, s1, c1;
    sincosf(a0, &s0, &c0);
    sincosf(a1, &s1, &c1);
    size_t base = (size_t)rt * HD;
    float q0 = g_q[base + d0], q1 = g_q[base + d1];
    g_q[base + d0] = q0 * c0 - q1 * s0;
    g_q[base + d1] = q1 * c1 + q0 * s1;
    float k0 = g_k[base + d0], k1 = g_k[base + d1];
    g_k[base + d0] = k0 * c0 - k1 * s0;
    g_k[base + d1] = k1 * c1 + k0 * s1;
}

// ---------------------------------------------------------------------------
// Bucket: proj = q . R[:,0,:], argmax over [proj, -proj]  (round-0 exact).
// ---------------------------------------------------------------------------
__global__ __launch_bounds__(128) void bucket_kernel(const float* __restrict__ R)
{
    __shared__ float Rs[64 * 32];
    int tid = threadIdx.x;
    for (int i = tid; i < 2048; i += 128) {
        int d = i >> 5, m = i & 31;
        Rs[i] = R[d * 64 + m];
    }
    __syncthreads();

    int idx = blockIdx.x * 128 + tid;
    float q[64];
    const float* qp = &g_q[(size_t)idx * HD];
#pragma unroll
    for (int l = 0; l < 16; l++) *(float4*)&q[l * 4] = *(const float4*)&qp[l * 4];

    float proj[32];
    for (int m = 0; m < 32; m++) {
        float s = 0.f;
#pragma unroll
        for (int d = 0; d < 64; d++) s += q[d] * Rs[d * 32 + m];
        proj[m] = s;
    }
    float best = -1e30f; int bi = 0;
#pragma unroll
    for (int i = 0; i < 64; i++) {
        float v = (i < 32) ? proj[i] : -proj[i - 32];
        if (v > best) { best = v; bi = i; }
    }
    g_keys[idx] = ((unsigned)bi << 12) | (unsigned)(idx & 4095);
}

// ---------------------------------------------------------------------------
// Per-(bh) bitonic sort of 4096 composite keys (== JAX stable argsort).
// ---------------------------------------------------------------------------
__global__ __launch_bounds__(1024) void sort_kernel()
{
    __shared__ unsigned s[4096];
    int bh = blockIdx.x, tid = threadIdx.x;
    for (int i = tid; i < 4096; i += 1024) s[i] = g_keys[bh * 4096 + i];
    __syncthreads();
    for (int k = 2; k <= 4096; k <<= 1) {
        for (int j = k >> 1; j > 0; j >>= 1) {
            for (int i = tid; i < 4096; i += 1024) {
                int ixj = i ^ j;
                if (ixj > i) {
                    unsigned a = s[i], b = s[ixj];
                    bool up = (i & k) == 0;
                    if ((a > b) == up) { s[i] = b; s[ixj] = a; }
                }
            }
            __syncthreads();
        }
    }
    for (int i = tid; i < 4096; i += 1024)
        g_sidx[bh * 4096 + i] = (int)(s[i] & 4095u);
}

// ---------------------------------------------------------------------------
// Fused gather + chunked softmax attention + unsort-scatter (round-0 exact).
// ---------------------------------------------------------------------------
#define ATTN_SMEM ((8192 + 8192 + 128 * 129) * 4)

__global__ __launch_bounds__(128) void attn_kernel()
{
    extern __shared__ float sm[];
    float* Ks = sm;                 // [128][64]
    float* Vs = sm + 8192;          // [128][64]
    float* Ss = sm + 16384;         // [128][129] padded
    __shared__ int sidx_s[128];

    int bc = blockIdx.x;
    int bh = bc >> 5;
    int c  = bc & 31;
    int p0 = c * 128;
    int tid = threadIdx.x;
    const int rowbase = bh * Tn;

    sidx_s[tid] = g_sidx[rowbase + p0 + tid];
    __syncthreads();

    for (int i = tid; i < 128 * 16; i += 128) {
        int r = i >> 4, l = (i & 15) * 4;
        size_t src = ((size_t)(rowbase + sidx_s[r])) * HD + l;
        *(float4*)&Ks[r * 64 + l] = *(const float4*)&g_k[src];
        *(float4*)&Vs[r * 64 + l] = *(const float4*)&g_v[src];
    }
    __syncthreads();

    int r  = tid;
    int si = sidx_s[r];
    float qr[64];
    {
        const float* qp = &g_q[((size_t)(rowbase + si)) * HD];
#pragma unroll
        for (int l = 0; l < 16; l++) *(float4*)&qr[l * 4] = *(const float4*)&qp[l * 4];
    }

    float mx = -1e30f;
    for (int j = 0; j < 128; j++) {
        const float* kp = &Ks[j * 64];
        float s0 = 0.f, s1 = 0.f, s2 = 0.f, s3 = 0.f;
#pragma unroll
        for (int d = 0; d < 64; d += 4) {
            float4 k4 = *(const float4*)&kp[d];
            s0 += qr[d + 0] * k4.x;
            s1 += qr[d + 1] * k4.y;
            s2 += qr[d + 2] * k4.z;
            s3 += qr[d + 3] * k4.w;
        }
        float s = (s0 + s1 + s2 + s3) * 0.125f;
        Ss[r * 129 + j] = s;
        mx = fmaxf(mx, s);
    }

    float sum = 0.f;
#pragma unroll 4
    for (int j = 0; j < 128; j++) {
        float e = __expf(Ss[r * 129 + j] - mx);
        Ss[r * 129 + j] = e;
        sum += e;
    }
    float inv = 1.0f / sum;

    float o[64];
#pragma unroll
    for (int d = 0; d < 64; d++) o[d] = 0.f;
    for (int j = 0; j < 128; j++) {
        float p = Ss[r * 129 + j];
        const float* vp = &Vs[j * 64];
#pragma unroll
        for (int d = 0; d < 64; d += 4) {
            float4 v4 = *(const float4*)&vp[d];
            o[d + 0] += p * v4.x;
            o[d + 1] += p * v4.y;
            o[d + 2] += p * v4.z;
            o[d + 3] += p * v4.w;
        }
    }

    int b = bh >> 4, h = bh & 15;
    float* op = &g_xo[((size_t)(b * Tn + si)) * Dn + h * HD];
#pragma unroll
    for (int l = 0; l < 16; l++) {
        float4 v4 = make_float4(o[l * 4 + 0] * inv, o[l * 4 + 1] * inv,
                                o[l * 4 + 2] * inv, o[l * 4 + 3] * inv);
        *(float4*)&op[l * 4] = v4;
    }
}

// ---------------------------------------------------------------------------
extern "C" void kernel_launch(void* const* d_in, const int* in_sizes, int n_in,
                              void* d_out, int out_size)
{
    const float* x      = (const float*)d_in[0];
    const float* W_attn = (const float*)d_in[1];
    const float* b_attn = (const float*)d_in[2];
    const float* W_proj = (const float*)d_in[3];
    const float* b_proj = (const float*)d_in[4];
    const float* R      = (const float*)d_in[5];
    float* out = (float*)d_out;

    cudaFuncSetAttribute(attn_kernel,
                         cudaFuncAttributeMaxDynamicSharedMemorySize, ATTN_SMEM);

    clear_flags_kernel<<<1, 1>>>();

    // Full QKV GEMM — double-buffered FFMA, bit-identical FMA order
    dim3 gq(24, Mn / 128);
    gemm_db_kernel<<<gq, 256>>>(x, W_attn, b_attn, nullptr, 3 * Dn, 1);
    check_qkv_kernel<<<(128 * 24 * 32 + 255) / 256, 256>>>(x, W_attn, b_attn);
    guard_qkv_kernel<<<gq, 256>>>(x, W_attn, b_attn);

    rope_kernel<<<(BH * Tn * 32 + 255) / 256, 256>>>();
    bucket_kernel<<<BH * Tn / 128, 128>>>(R);
    sort_kernel<<<BH, 1024>>>();
    attn_kernel<<<BH * NCH, 128, ATTN_SMEM>>>();

    // Output projection — double-buffered FFMA + verify + fallback
    dim3 go(8, Mn / 128);
    gemm_db_kernel<<<go, 256>>>(g_xo, W_proj, b_proj, out, Dn, 0);
    check_proj_kernel<<<(128 * 8 * 32 + 255) / 256, 256>>>(W_proj, b_proj, out);
    guard_proj_kernel<<<go, 256>>>(W_proj, b_proj, out);
}

// round 17
// speedup vs baseline: 1.9077x; 1.9077x over previous
#include <cuda_runtime.h>
#include <cuda_bf16.h>
#include <math.h>
#include <stdint.h>

// Problem constants
#define Bn   4
#define Tn   4096
#define Dn   1024
#define Hn   16
#define HD   64
#define BH   64            // Bn*Hn
#define NCH  32            // Tn/128
#define Mn   16384         // Bn*Tn

// tcgen05 only on arch-specific passes; plain compute_103 pass gets a stub.
#if defined(__CUDA_ARCH_FEAT_SM103_ALL) || defined(__CUDA_ARCH_FEAT_SM100_ALL) || \
    defined(__CUDA_ARCH_FEAT_SM101_ALL) || defined(__CUDA_ARCH_FEAT_SM110_ALL) || \
    (defined(__CUDA_ARCH_FAMILY_SPECIFIC__) && (__CUDA_ARCH_FAMILY_SPECIFIC__ >= 1000))
#define HAS_TC 1
#else
#define HAS_TC 0
#endif

// Scratch (device globals; no allocations allowed)
static __device__ float    g_q[(size_t)BH * Tn * HD];
static __device__ float    g_k[(size_t)BH * Tn * HD];
static __device__ float    g_v[(size_t)BH * Tn * HD];
static __device__ float    g_xo[(size_t)Mn * Dn];
static __device__ unsigned g_keys[BH * Tn];
static __device__ int      g_sidx[BH * Tn];
static __device__ int      g_flags[2];

// ---------------------------------------------------------------------------
#define SMEM_SWIZZLE_128B(bo) ((bo) ^ (((bo) >> 3) & 0x70))

__device__ __forceinline__ void split_bf16(float v, uint16_t& hi, uint16_t& lo) {
    uint16_t h = __bfloat16_as_ushort(__float2bfloat16(v));
    float hf = __uint_as_float((uint32_t)h << 16);
    lo = __bfloat16_as_ushort(__float2bfloat16(v - hf));
    hi = h;
}
__device__ __forceinline__ void pack2_bf16(float a, float b,
                                           uint32_t& hi, uint32_t& lo) {
    uint16_t h0, l0, h1, l1;
    split_bf16(a, h0, l0);
    split_bf16(b, h1, l1);
    hi = (uint32_t)h0 | ((uint32_t)h1 << 16);
    lo = (uint32_t)l0 | ((uint32_t)l1 << 16);
}

#if HAS_TC
__device__ __forceinline__ uint32_t elect_one_pred() {
    uint32_t pred;
    asm volatile("{\n\t.reg .pred p;\n\telect.sync _|p, 0xFFFFFFFF;\n\t"
                 "selp.b32 %0, 1, 0, p;\n\t}" : "=r"(pred));
    return pred;
}
__device__ __forceinline__ uint32_t smem_to_u32(const void* p) {
    uint32_t a;
    asm("{ .reg .u64 t; cvta.to.shared.u64 t, %1; cvt.u32.u64 %0, t; }"
        : "=r"(a) : "l"(p));
    return a;
}

static constexpr uint64_t SMEM_DESC_BASE_SW128 =
    (uint64_t(2)  << 61) | (uint64_t(1) << 46) | (uint64_t(64) << 32) | (uint64_t(1) << 16);
#define MAKE_SMEM_DESC(base_addr) \
    (SMEM_DESC_BASE_SW128 | ((uint64_t)((base_addr) >> 4) & 0x3FFF))

#define TCGEN05_ALLOC(smem_result_addr, nCols) \
    asm volatile("tcgen05.alloc.cta_group::1.sync.aligned.shared::cta.b32 [%0], %1;" \
        :: "r"((uint32_t)(smem_result_addr)), "r"((uint32_t)(nCols)) : "memory")
#define TCGEN05_RELINQUISH() \
    asm volatile("tcgen05.relinquish_alloc_permit.cta_group::1.sync.aligned;")
#define TCGEN05_DEALLOC(tmem_addr, nCols) \
    asm volatile("tcgen05.dealloc.cta_group::1.sync.aligned.b32 %0, %1;" \
        :: "r"(tmem_addr), "r"((uint32_t)(nCols)))
#define TCGEN05_COMMIT(mbar) \
    asm volatile("tcgen05.commit.cta_group::1.mbarrier::arrive::one.shared::cluster.b64 [%0];" \
        :: "r"((uint32_t)(mbar)) : "memory")
#define TCGEN05_FENCE_AFTER() \
    asm volatile("tcgen05.fence::after_thread_sync;" ::: "memory")
#define TCGEN05_FENCE_BEFORE() \
    asm volatile("tcgen05.fence::before_thread_sync;" ::: "memory")
#define TCGEN05_WAIT_LD() \
    asm volatile("tcgen05.wait::ld.sync.aligned;" ::: "memory")
#define TCGEN05_WAIT_ST() \
    asm volatile("tcgen05.wait::st.sync.aligned;" ::: "memory")

#define MBARRIER_INIT(mbar, count) \
    asm volatile("mbarrier.init.shared.b64 [%0], %1;" \
        :: "r"((uint32_t)(mbar)), "r"((uint32_t)(count)) : "memory")
#define MBARRIER_WAIT_PARITY(mbar_smem_addr, phase_parity) do { \
    uint32_t _mbar = (uint32_t)(mbar_smem_addr); \
    uint32_t _parity = (uint32_t)(phase_parity); \
    uint32_t _done; \
    asm volatile("{\n\t.reg .pred p;\n\t" \
        "mbarrier.try_wait.parity.acquire.cta.shared::cta.b64 p, [%1], %2;\n\t" \
        "selp.b32 %0, 1, 0, p;\n\t}" \
        : "=r"(_done) : "r"(_mbar), "r"(_parity) : "memory"); \
    if (!_done) { \
        asm volatile("{\n\t.reg .pred P1;\n\t" \
            "WAIT_LOOP_%=:\n\t" \
            "mbarrier.try_wait.parity.acquire.cta.shared::cta.b64 P1, [%0], %1, 0x989680;\n\t" \
            "@P1 bra.uni WAIT_DONE_%=;\n\t" \
            "bra.uni WAIT_LOOP_%=;\n\t" \
            "WAIT_DONE_%=:\n\t}" \
            :: "r"(_mbar), "r"(_parity) : "memory"); \
    } \
} while(0)

#define TCGEN05_LD_32X32B_X32(r, tmem_addr) \
    asm volatile("tcgen05.ld.sync.aligned.32x32b.x32.b32 " \
        "{%0, %1, %2, %3, %4, %5, %6, %7, %8, %9, %10, %11, %12, %13, %14, %15, " \
        " %16, %17, %18, %19, %20, %21, %22, %23, %24, %25, %26, %27, %28, %29, %30, %31}, [%32];" \
        : "=r"((r)[0]),  "=r"((r)[1]),  "=r"((r)[2]),  "=r"((r)[3]), \
          "=r"((r)[4]),  "=r"((r)[5]),  "=r"((r)[6]),  "=r"((r)[7]), \
          "=r"((r)[8]),  "=r"((r)[9]),  "=r"((r)[10]), "=r"((r)[11]), \
          "=r"((r)[12]), "=r"((r)[13]), "=r"((r)[14]), "=r"((r)[15]), \
          "=r"((r)[16]), "=r"((r)[17]), "=r"((r)[18]), "=r"((r)[19]), \
          "=r"((r)[20]), "=r"((r)[21]), "=r"((r)[22]), "=r"((r)[23]), \
          "=r"((r)[24]), "=r"((r)[25]), "=r"((r)[26]), "=r"((r)[27]), \
          "=r"((r)[28]), "=r"((r)[29]), "=r"((r)[30]), "=r"((r)[31]) \
        : "r"(tmem_addr))

#define TCGEN05_ST_32X32B_X32(tmem_addr, r) \
    asm volatile("tcgen05.st.sync.aligned.32x32b.x32.b32 [%0], " \
        "{%1, %2, %3, %4, %5, %6, %7, %8, %9, %10, %11, %12, %13, %14, %15, %16, " \
        " %17, %18, %19, %20, %21, %22, %23, %24, %25, %26, %27, %28, %29, %30, %31, %32};" \
        :: "r"(tmem_addr), \
           "r"((r)[0]),  "r"((r)[1]),  "r"((r)[2]),  "r"((r)[3]), \
           "r"((r)[4]),  "r"((r)[5]),  "r"((r)[6]),  "r"((r)[7]), \
           "r"((r)[8]),  "r"((r)[9]),  "r"((r)[10]), "r"((r)[11]), \
           "r"((r)[12]), "r"((r)[13]), "r"((r)[14]), "r"((r)[15]), \
           "r"((r)[16]), "r"((r)[17]), "r"((r)[18]), "r"((r)[19]), \
           "r"((r)[20]), "r"((r)[21]), "r"((r)[22]), "r"((r)[23]), \
           "r"((r)[24]), "r"((r)[25]), "r"((r)[26]), "r"((r)[27]), \
           "r"((r)[28]), "r"((r)[29]), "r"((r)[30]), "r"((r)[31]) \
        : "memory")

// TS-form bf16 MMA — verified working (R7/R12).
#define TCGEN05_MMA_F16_TS(d_tmem, a_tmem, b_desc, idesc, enable_d) do { \
    uint32_t _enable = (enable_d) ? 1 : 0; \
    uint32_t _zero = 0; \
    asm volatile( \
        "{\n\t" \
        ".reg .pred p;\n\t" \
        "setp.ne.u32 p, %6, 0;\n\t" \
        "tcgen05.mma.cta_group::1.kind::f16 [%0], [%1], %2, %3, " \
        "{%4, %4, %4, %4}, p;\n\t" \
        "}" \
        :: "r"(d_tmem), "r"(a_tmem), "l"(b_desc), "r"(idesc), \
           "r"(_zero), "r"(_zero), "r"(_enable) \
        : "memory"); \
} while(0)

#define BF16_IDESC_N32 0x8080490u
#endif  // HAS_TC

// ---------------------------------------------------------------------------
__global__ void clear_flags_kernel() { g_flags[0] = 0; g_flags[1] = 0; }

// ---------------------------------------------------------------------------
// tc GEMM body (R12-verified, 6441us config) as a device function.
// Computes one 128x128 tile of A @ W cols [bn, bn+128) with 3-term bf16.
// ---------------------------------------------------------------------------
#define TC_SMEM 68608

__device__ __forceinline__ void tc_tile_body(
    char* smem, const float* __restrict__ A, const float* __restrict__ W,
    const float* __restrict__ bias, float* __restrict__ C,
    int N_total, int bm, int bn, int scatter)
{
#if HAS_TC
    int tid = threadIdx.x;
    uint32_t sb = smem_to_u32(smem);
    int wid = tid >> 5, lid = tid & 31;

    if (wid == 0) {
        TCGEN05_ALLOC(sb, 256);
        TCGEN05_RELINQUISH();        // R12-isolated fix
    }
    if (tid == 0) MBARRIER_INIT(sb + 16, 1);
    __syncthreads();
    uint32_t tmem;
    asm volatile("ld.shared.b32 %0, [%1];" : "=r"(tmem) : "r"(sb));

    uint32_t* const Ahs = (uint32_t*)(smem + 1024);
    uint32_t* const Als = (uint32_t*)(smem + 18432);
    const uint32_t oBh = 35840, oBl = 52224;
    char* const pBh = smem + oBh;
    char* const pBl = smem + oBl;

    for (int c = 0; c < 16; c++) {              // K chunks of 64
        int k0 = c * 64;

        float4 av[8], bv[8];
#pragma unroll
        for (int i = 0; i < 8; i++) {
            int e  = tid + 256 * i;
            int r  = e >> 4, c4 = e & 15;
            av[i] = *(const float4*)&A[(size_t)(bm + r) * 1024 + k0 + c4 * 4];
            int kk = e >> 5, ng = e & 31;
            bv[i] = *(const float4*)&W[(size_t)(k0 + kk) * N_total + bn + ng * 4];
        }

#pragma unroll
        for (int i = 0; i < 8; i++) {
            int e = tid + 256 * i;
            {
                int r = e >> 4, c4 = e & 15;
                uint32_t h0, l0, h1, l1;
                pack2_bf16(av[i].x, av[i].y, h0, l0);
                pack2_bf16(av[i].z, av[i].w, h1, l1);
                int base = r * 33 + c4 * 2;
                Ahs[base] = h0;  Ahs[base + 1] = h1;
                Als[base] = l0;  Als[base + 1] = l1;
            }
            {
                int kk = e >> 5, ng = e & 31;
                float vals[4] = { bv[i].x, bv[i].y, bv[i].z, bv[i].w };
#pragma unroll
                for (int t = 0; t < 4; t++) {
                    int n  = ng * 4 + t;
                    int nt = n >> 5, nr = n & 31;
                    uint16_t h, l;
                    split_bf16(vals[t], h, l);
                    uint32_t o2 = nt * 4096 + SMEM_SWIZZLE_128B((uint32_t)(nr * 128 + kk * 2));
                    *(uint16_t*)(pBh + o2) = h;
                    *(uint16_t*)(pBl + o2) = l;
                }
            }
        }
        __syncthreads();

        if (tid < 128) {
            uint32_t hi[32], lo[32];
            const uint32_t* bh = &Ahs[tid * 33];
            const uint32_t* bl = &Als[tid * 33];
#pragma unroll
            for (int j = 0; j < 32; j++) { hi[j] = bh[j]; lo[j] = bl[j]; }
            uint32_t wofs = ((uint32_t)(tid >> 5)) << 21;
            TCGEN05_ST_32X32B_X32(tmem + 128 + wofs, hi);
            TCGEN05_ST_32X32B_X32(tmem + 160 + wofs, lo);
            TCGEN05_WAIT_ST();
        }
        __syncthreads();

        if (wid == 0) {
            uint64_t dbh = MAKE_SMEM_DESC(sb + oBh);
            uint64_t dbl = MAKE_SMEM_DESC(sb + oBl);
            if (elect_one_pred()) {
#pragma unroll
                for (int ks = 0; ks < 4; ks++) {
                    uint32_t ah = tmem + 128 + ks * 8;
                    uint32_t al = tmem + 160 + ks * 8;
#pragma unroll
                    for (int nt = 0; nt < 4; nt++) {
                        uint32_t d  = tmem + nt * 32;
                        uint64_t bo = (uint64_t)(nt * 256) + ks * 2;
                        uint32_t en0 = (c > 0 || ks > 0) ? 1u : 0u;
                        TCGEN05_MMA_F16_TS(d, ah, dbh + bo, BF16_IDESC_N32, en0);
                        TCGEN05_MMA_F16_TS(d, ah, dbl + bo, BF16_IDESC_N32, 1u);
                        TCGEN05_MMA_F16_TS(d, al, dbh + bo, BF16_IDESC_N32, 1u);
                    }
                }
                TCGEN05_COMMIT(sb + 16);
            }
        }
        MBARRIER_WAIT_PARITY(sb + 16, c & 1);
        TCGEN05_FENCE_AFTER();
        __syncthreads();
    }

    if (wid < 4) {
        int m = bm + wid * 32 + lid;
        int b = m >> 12, t = m & 4095;
#pragma unroll
        for (int g = 0; g < 4; g++) {
            uint32_t r[32];
            TCGEN05_LD_32X32B_X32(r, tmem + g * 32);
            TCGEN05_WAIT_LD();
            int ncol0 = bn + g * 32;
            if (scatter) {
                int which = ncol0 >> 10;               // 1 = k, 2 = v
                float* dst = (which == 1) ? g_k : g_v;
#pragma unroll
                for (int jj = 0; jj < 32; jj += 4) {
                    int n0 = ncol0 + jj;
                    int h = (n0 & 1023) >> 6, j0 = n0 & 63;
                    float* p = dst + (((size_t)(b * Hn + h) * Tn) + t) * HD + j0;
                    float4 v;
                    v.x = __uint_as_float(r[jj + 0]) + bias[n0 + 0];
                    v.y = __uint_as_float(r[jj + 1]) + bias[n0 + 1];
                    v.z = __uint_as_float(r[jj + 2]) + bias[n0 + 2];
                    v.w = __uint_as_float(r[jj + 3]) + bias[n0 + 3];
                    *(float4*)p = v;
                }
            } else {
                float* p = C + (size_t)m * 1024 + ncol0;
#pragma unroll
                for (int jj = 0; jj < 32; jj += 4) {
                    float4 v;
                    v.x = __uint_as_float(r[jj + 0]) + bias[ncol0 + jj + 0];
                    v.y = __uint_as_float(r[jj + 1]) + bias[ncol0 + jj + 1];
                    v.z = __uint_as_float(r[jj + 2]) + bias[ncol0 + jj + 2];
                    v.w = __uint_as_float(r[jj + 3]) + bias[ncol0 + jj + 3];
                    *(float4*)&p[jj] = v;
                }
            }
        }
        TCGEN05_FENCE_BEFORE();
    }
    __syncthreads();
    if (wid == 0) TCGEN05_DEALLOC(tmem, 256);
#else
    (void)smem; (void)A; (void)W; (void)bias; (void)C;
    (void)N_total; (void)bm; (void)bn; (void)scatter;
#endif
}

// ---------------------------------------------------------------------------
// Q-FFMA tile body (round-0 exact numerics; writes g_q head layout).
// Uses the dynamic SMEM region (first 8KB).
// ---------------------------------------------------------------------------
__device__ __forceinline__ void q_ffma_tile_body(
    char* smem, const float* __restrict__ X, const float* __restrict__ W,
    const float* __restrict__ bias, int bm, int bn)
{
    const int K = Dn, N = 3 * Dn;
    float* As = (float*)smem;                 // [8][128]
    float* Bs = (float*)(smem + 4096);        // [8][128]
    int tid = threadIdx.x;
    int arow = tid >> 1,  acol = (tid & 1) << 2;
    int brow = tid >> 5,  bcol = (tid & 31) << 2;
    const float* Ap = X + (size_t)(bm + arow) * K + acol;
    const float* Bp = W + (size_t)brow * N + bn + bcol;
    int ty = tid >> 4, tx = tid & 15;

    float acc[8][8];
#pragma unroll
    for (int i = 0; i < 8; i++)
#pragma unroll
        for (int j = 0; j < 8; j++) acc[i][j] = 0.f;

    for (int k0 = 0; k0 < K; k0 += 8) {
        float4 a4 = *(const float4*)Ap;
        float4 b4 = *(const float4*)Bp;
        As[(acol + 0) * 128 + arow] = a4.x;
        As[(acol + 1) * 128 + arow] = a4.y;
        As[(acol + 2) * 128 + arow] = a4.z;
        As[(acol + 3) * 128 + arow] = a4.w;
        *(float4*)&Bs[brow * 128 + bcol] = b4;
        __syncthreads();
#pragma unroll
        for (int kk = 0; kk < 8; kk++) {
            float a[8], b[8];
            *(float4*)&a[0] = *(const float4*)&As[kk * 128 + ty * 8];
            *(float4*)&a[4] = *(const float4*)&As[kk * 128 + ty * 8 + 4];
            *(float4*)&b[0] = *(const float4*)&Bs[kk * 128 + tx * 8];
            *(float4*)&b[4] = *(const float4*)&Bs[kk * 128 + tx * 8 + 4];
#pragma unroll
            for (int i = 0; i < 8; i++)
#pragma unroll
                for (int j = 0; j < 8; j++) acc[i][j] += a[i] * b[j];
        }
        __syncthreads();
        Ap += 8;
        Bp += (size_t)8 * N;
    }

    int n0 = bn + tx * 8;                    // < 1024 -> Q
    int h  = (n0 & 1023) >> 6;
    int j0 = n0 & 63;
    float bb[8];
#pragma unroll
    for (int j = 0; j < 8; j++) bb[j] = bias[n0 + j];
#pragma unroll
    for (int i = 0; i < 8; i++) {
        int m = bm + ty * 8 + i;
        int b = m >> 12;
        int t = m & 4095;
        float* row = g_q + (((size_t)(b * Hn + h) * Tn) + t) * HD + j0;
#pragma unroll
        for (int j = 0; j < 8; j++) row[j] = acc[i][j] + bb[j];
    }
}

// ---------------------------------------------------------------------------
// Fused heterogeneous QKV kernel: 3072 blocks, interleaved 2:1.
//   bz%3 < 2  -> tc-KV tile   (2048 tiles: 16 x 128)
//   bz%3 == 2 -> Q-FFMA tile  (1024 tiles:  8 x 128)
// Q hides under KV since the paths use complementary pipes.
// ---------------------------------------------------------------------------
__global__ __launch_bounds__(256, 2) void fused_qkv_kernel(
    const float* __restrict__ x, const float* __restrict__ W_attn,
    const float* __restrict__ b_attn)
{
    extern __shared__ char smem[];
    int bz = blockIdx.x;
    int g = bz / 3, r = bz % 3;
    if (r == 2) {
        // Q tile index g in [0,1024): bx = g & 7, by = g >> 3
        int bm = (g >> 3) * 128, bn = (g & 7) * 128;
        q_ffma_tile_body(smem, x, W_attn, b_attn, bm, bn);
    } else {
        // KV tile index ti = g*2 + r in [0,2048): bx = ti & 15, by = ti >> 4
        int ti = g * 2 + r;
        int bm = (ti >> 4) * 128, bn = 1024 + (ti & 15) * 128;
        tc_tile_body(smem, x, W_attn, b_attn, nullptr, 3 * Dn, bm, bn, 1);
    }
}

// Output-projection tc kernel (R12 launch shape: grid (8, 128)).
__global__ __launch_bounds__(256, 2) void tc_proj_kernel(
    const float* __restrict__ W, const float* __restrict__ bias,
    float* __restrict__ C)
{
    extern __shared__ char smem[];
    int bm = blockIdx.y * 128, bn = blockIdx.x * 128;
    tc_tile_body(smem, g_xo, W, bias, C, Dn, bm, bn, 0);
}

// ---------------------------------------------------------------------------
// Check kernels (sampled verification; 1 warp / tile, 32 elements).
// ---------------------------------------------------------------------------
__global__ __launch_bounds__(256) void check_kv_kernel(
    const float* __restrict__ x, const float* __restrict__ W,
    const float* __restrict__ bias)
{
    int w = (blockIdx.x * blockDim.x + threadIdx.x) >> 5;
    int lane = threadIdx.x & 31;
    if (w >= 128 * 16) return;
    int ty = w >> 4, tx = w & 15;
    int m  = ty * 128 + ((ty * 7 + tx * 3) & 127);
    int n0 = 1024 + tx * 128 + ((ty * 29 + tx * 13) & 96);
    int n  = n0 + lane;
    float acc = bias[n];
    const float* xr = &x[(size_t)m * 1024];
    for (int k = 0; k < 1024; k++)
        acc += xr[k] * W[(size_t)k * 3072 + n];
    int which = n >> 10;
    const float* dst = (which == 1) ? g_k : g_v;
    int h = (n & 1023) >> 6, j0 = n & 63, b = m >> 12, t = m & 4095;
    float got = dst[(((size_t)(b * Hn + h) * Tn) + t) * HD + j0];
    float diff = fabsf(got - acc);
    if (!(diff <= 3e-3f * (1.0f + fabsf(acc)))) atomicExch(&g_flags[0], 1);
}

__global__ __launch_bounds__(256) void check_proj_kernel(
    const float* __restrict__ W, const float* __restrict__ bias,
    const float* __restrict__ out)
{
    int w = (blockIdx.x * blockDim.x + threadIdx.x) >> 5;
    int lane = threadIdx.x & 31;
    if (w >= 128 * 8) return;
    int ty = w >> 3, tx = w & 7;
    int m  = ty * 128 + ((ty * 7 + tx * 3) & 127);
    int n  = tx * 128 + ((ty * 29 + tx * 13) & 96) + lane;
    float acc = bias[n];
    const float* xr = &g_xo[(size_t)m * 1024];
    for (int k = 0; k < 1024; k++)
        acc += xr[k] * W[(size_t)k * 1024 + n];
    float got = out[(size_t)m * 1024 + n];
    float diff = fabsf(got - acc);
    if (!(diff <= 3e-3f * (1.0f + fabsf(acc)))) atomicExch(&g_flags[1], 1);
}

// ---------------------------------------------------------------------------
// Guard GEMMs (flag-gated FFMA recompute).
// ---------------------------------------------------------------------------
__global__ __launch_bounds__(256) void guard_kv_kernel(
    const float* __restrict__ X, const float* __restrict__ W,
    const float* __restrict__ bias)
{
    if (*(volatile int*)&g_flags[0] == 0) return;
    const int K = Dn, N = 3 * Dn;
    __shared__ float As[8][128];
    __shared__ float Bs[8][128];
    int tid = threadIdx.x;
    int bm = blockIdx.y * 128;
    int bn = 1024 + blockIdx.x * 128;
    int arow = tid >> 1,  acol = (tid & 1) << 2;
    int brow = tid >> 5,  bcol = (tid & 31) << 2;
    const float* Ap = X + (size_t)(bm + arow) * K + acol;
    const float* Bp = W + (size_t)brow * N + bn + bcol;
    int ty = tid >> 4, tx = tid & 15;
    float acc[8][8];
#pragma unroll
    for (int i = 0; i < 8; i++)
#pragma unroll
        for (int j = 0; j < 8; j++) acc[i][j] = 0.f;
    for (int k0 = 0; k0 < K; k0 += 8) {
        float4 a4 = *(const float4*)Ap;
        float4 b4 = *(const float4*)Bp;
        As[acol + 0][arow] = a4.x;
        As[acol + 1][arow] = a4.y;
        As[acol + 2][arow] = a4.z;
        As[acol + 3][arow] = a4.w;
        *(float4*)&Bs[brow][bcol] = b4;
        __syncthreads();
#pragma unroll
        for (int kk = 0; kk < 8; kk++) {
            float a[8], b[8];
            *(float4*)&a[0] = *(const float4*)&As[kk][ty * 8];
            *(float4*)&a[4] = *(const float4*)&As[kk][ty * 8 + 4];
            *(float4*)&b[0] = *(const float4*)&Bs[kk][tx * 8];
            *(float4*)&b[4] = *(const float4*)&Bs[kk][tx * 8 + 4];
#pragma unroll
            for (int i = 0; i < 8; i++)
#pragma unroll
                for (int j = 0; j < 8; j++) acc[i][j] += a[i] * b[j];
        }
        __syncthreads();
        Ap += 8;
        Bp += (size_t)8 * N;
    }
    int n0 = bn + tx * 8;
    int which = n0 >> 10;
    float* dst = (which == 1) ? g_k : g_v;
    int h = (n0 & 1023) >> 6, j0 = n0 & 63;
    float bb[8];
#pragma unroll
    for (int j = 0; j < 8; j++) bb[j] = bias[n0 + j];
#pragma unroll
    for (int i = 0; i < 8; i++) {
        int m = bm + ty * 8 + i;
        int b = m >> 12, t = m & 4095;
        float* row = dst + (((size_t)(b * Hn + h) * Tn) + t) * HD + j0;
#pragma unroll
        for (int j = 0; j < 8; j++) row[j] = acc[i][j] + bb[j];
    }
}

__global__ __launch_bounds__(256) void guard_proj_kernel(
    const float* __restrict__ W, const float* __restrict__ bias,
    float* __restrict__ C)
{
    if (*(volatile int*)&g_flags[1] == 0) return;
    const int K = Dn, N = Dn;
    __shared__ float As[8][128];
    __shared__ float Bs[8][128];
    int tid = threadIdx.x;
    int bm = blockIdx.y * 128;
    int bn = blockIdx.x * 128;
    int arow = tid >> 1,  acol = (tid & 1) << 2;
    int brow = tid >> 5,  bcol = (tid & 31) << 2;
    const float* Ap = g_xo + (size_t)(bm + arow) * K + acol;
    const float* Bp = W + (size_t)brow * N + bn + bcol;
    int ty = tid >> 4, tx = tid & 15;
    float acc[8][8];
#pragma unroll
    for (int i = 0; i < 8; i++)
#pragma unroll
        for (int j = 0; j < 8; j++) acc[i][j] = 0.f;
    for (int k0 = 0; k0 < K; k0 += 8) {
        float4 a4 = *(const float4*)Ap;
        float4 b4 = *(const float4*)Bp;
        As[acol + 0][arow] = a4.x;
        As[acol + 1][arow] = a4.y;
        As[acol + 2][arow] = a4.z;
        As[acol + 3][arow] = a4.w;
        *(float4*)&Bs[brow][bcol] = b4;
        __syncthreads();
#pragma unroll
        for (int kk = 0; kk < 8; kk++) {
            float a[8], b[8];
            *(float4*)&a[0] = *(const float4*)&As[kk][ty * 8];
            *(float4*)&a[4] = *(const float4*)&As[kk][ty * 8 + 4];
            *(float4*)&b[0] = *(const float4*)&Bs[kk][tx * 8];
            *(float4*)&b[4] = *(const float4*)&Bs[kk][tx * 8 + 4];
#pragma unroll
            for (int i = 0; i < 8; i++)
#pragma unroll
                for (int j = 0; j < 8; j++) acc[i][j] += a[i] * b[j];
        }
        __syncthreads();
        Ap += 8;
        Bp += (size_t)8 * N;
    }
    float bb[8];
#pragma unroll
    for (int j = 0; j < 8; j++) bb[j] = bias[bn + tx * 8 + j];
#pragma unroll
    for (int i = 0; i < 8; i++) {
        int m = bm + ty * 8 + i;
        float* row = C + (size_t)m * N + bn + tx * 8;
#pragma unroll
        for (int j = 0; j < 8; j++) row[j] = acc[i][j] + bb[j];
    }
}

// ---------------------------------------------------------------------------
__global__ void rope_kernel()
{
    int idx = blockIdx.x * blockDim.x + threadIdx.x;
    if (idx >= BH * Tn * 32) return;
    int p  = idx & 31;
    int rt = idx >> 5;
    int t  = rt & 4095;
    int d0 = p * 2, d1 = p * 2 + 1;
    float e0 = (float)(d0 & 31) * (1.0f / 32.0f);
    float e1 = (float)(d1 & 31) * (1.0f / 32.0f);
    float inv0 = 1.0f / powf(10000.0f, e0);
    float inv1 = 1.0f / powf(10000.0f, e1);
    float a0 = (float)t * inv0, a1 = (float)t * inv1;
    float s0, c0, s1, c1;
    sincosf(a0, &s0, &c0);
    sincosf(a1, &s1, &c1);
    size_t base = (size_t)rt * HD;
    float q0 = g_q[base + d0], q1 = g_q[base + d1];
    g_q[base + d0] = q0 * c0 - q1 * s0;
    g_q[base + d1] = q1 * c1 + q0 * s1;
    float k0 = g_k[base + d0], k1 = g_k[base + d1];
    g_k[base + d0] = k0 * c0 - k1 * s0;
    g_k[base + d1] = k1 * c1 + k0 * s1;
}

// ---------------------------------------------------------------------------
__global__ __launch_bounds__(128) void bucket_kernel(const float* __restrict__ R)
{
    __shared__ float Rs[64 * 32];
    int tid = threadIdx.x;
    for (int i = tid; i < 2048; i += 128) {
        int d = i >> 5, m = i & 31;
        Rs[i] = R[d * 64 + m];
    }
    __syncthreads();

    int idx = blockIdx.x * 128 + tid;
    float q[64];
    const float* qp = &g_q[(size_t)idx * HD];
#pragma unroll
    for (int l = 0; l < 16; l++) *(float4*)&q[l * 4] = *(const float4*)&qp[l * 4];

    float proj[32];
    for (int m = 0; m < 32; m++) {
        float s = 0.f;
#pragma unroll
        for (int d = 0; d < 64; d++) s += q[d] * Rs[d * 32 + m];
        proj[m] = s;
    }
    float best = -1e30f; int bi = 0;
#pragma unroll
    for (int i = 0; i < 64; i++) {
        float v = (i < 32) ? proj[i] : -proj[i - 32];
        if (v > best) { best = v; bi = i; }
    }
    g_keys[idx] = ((unsigned)bi << 12) | (unsigned)(idx & 4095);
}

// ---------------------------------------------------------------------------
__global__ __launch_bounds__(1024) void sort_kernel()
{
    __shared__ unsigned s[4096];
    int bh = blockIdx.x, tid = threadIdx.x;
    for (int i = tid; i < 4096; i += 1024) s[i] = g_keys[bh * 4096 + i];
    __syncthreads();
    for (int k = 2; k <= 4096; k <<= 1) {
        for (int j = k >> 1; j > 0; j >>= 1) {
            for (int i = tid; i < 4096; i += 1024) {
                int ixj = i ^ j;
                if (ixj > i) {
                    unsigned a = s[i], b = s[ixj];
                    bool up = (i & k) == 0;
                    if ((a > b) == up) { s[i] = b; s[ixj] = a; }
                }
            }
            __syncthreads();
        }
    }
    for (int i = tid; i < 4096; i += 1024)
        g_sidx[bh * 4096 + i] = (int)(s[i] & 4095u);
}

// ---------------------------------------------------------------------------
#define ATTN_SMEM ((8192 + 8192 + 128 * 129) * 4)

__global__ __launch_bounds__(128) void attn_kernel()
{
    extern __shared__ float sm[];
    float* Ks = sm;
    float* Vs = sm + 8192;
    float* Ss = sm + 16384;
    __shared__ int sidx_s[128];

    int bc = blockIdx.x;
    int bh = bc >> 5;
    int c  = bc & 31;
    int p0 = c * 128;
    int tid = threadIdx.x;
    const int rowbase = bh * Tn;

    sidx_s[tid] = g_sidx[rowbase + p0 + tid];
    __syncthreads();

    for (int i = tid; i < 128 * 16; i += 128) {
        int r = i >> 4, l = (i & 15) * 4;
        size_t src = ((size_t)(rowbase + sidx_s[r])) * HD + l;
        *(float4*)&Ks[r * 64 + l] = *(const float4*)&g_k[src];
        *(float4*)&Vs[r * 64 + l] = *(const float4*)&g_v[src];
    }
    __syncthreads();

    int r  = tid;
    int si = sidx_s[r];
    float qr[64];
    {
        const float* qp = &g_q[((size_t)(rowbase + si)) * HD];
#pragma unroll
        for (int l = 0; l < 16; l++) *(float4*)&qr[l * 4] = *(const float4*)&qp[l * 4];
    }

    float mx = -1e30f;
    for (int j = 0; j < 128; j++) {
        const float* kp = &Ks[j * 64];
        float s0 = 0.f, s1 = 0.f, s2 = 0.f, s3 = 0.f;
#pragma unroll
        for (int d = 0; d < 64; d += 4) {
            float4 k4 = *(const float4*)&kp[d];
            s0 += qr[d + 0] * k4.x;
            s1 += qr[d + 1] * k4.y;
            s2 += qr[d + 2] * k4.z;
            s3 += qr[d + 3] * k4.w;
        }
        float s = (s0 + s1 + s2 + s3) * 0.125f;
        Ss[r * 129 + j] = s;
        mx = fmaxf(mx, s);
    }

    float sum = 0.f;
#pragma unroll 4
    for (int j = 0; j < 128; j++) {
        float e = __expf(Ss[r * 129 + j] - mx);
        Ss[r * 129 + j] = e;
        sum += e;
    }
    float inv = 1.0f / sum;

    float o[64];
#pragma unroll
    for (int d = 0; d < 64; d++) o[d] = 0.f;
    for (int j = 0; j < 128; j++) {
        float p = Ss[r * 129 + j];
        const float* vp = &Vs[j * 64];
#pragma unroll
        for (int d = 0; d < 64; d += 4) {
            float4 v4 = *(const float4*)&vp[d];
            o[d + 0] += p * v4.x;
            o[d + 1] += p * v4.y;
            o[d + 2] += p * v4.z;
            o[d + 3] += p * v4.w;
        }
    }

    int b = bh >> 4, h = bh & 15;
    float* op = &g_xo[((size_t)(b * Tn + si)) * Dn + h * HD];
#pragma unroll
    for (int l = 0; l < 16; l++) {
        float4 v4 = make_float4(o[l * 4 + 0] * inv, o[l * 4 + 1] * inv,
                                o[l * 4 + 2] * inv, o[l * 4 + 3] * inv);
        *(float4*)&op[l * 4] = v4;
    }
}

// ---------------------------------------------------------------------------
extern "C" void kernel_launch(void* const* d_in, const int* in_sizes, int n_in,
                              void* d_out, int out_size)
{
    const float* x      = (const float*)d_in[0];
    const float* W_attn = (const float*)d_in[1];
    const float* b_attn = (const float*)d_in[2];
    const float* W_proj = (const float*)d_in[3];
    const float* b_proj = (const float*)d_in[4];
    const float* R      = (const float*)d_in[5];
    float* out = (float*)d_out;

    cudaFuncSetAttribute(attn_kernel,
                         cudaFuncAttributeMaxDynamicSharedMemorySize, ATTN_SMEM);
    cudaFuncSetAttribute(fused_qkv_kernel,
                         cudaFuncAttributeMaxDynamicSharedMemorySize, TC_SMEM);
    cudaFuncSetAttribute(tc_proj_kernel,
                         cudaFuncAttributeMaxDynamicSharedMemorySize, TC_SMEM);

    clear_flags_kernel<<<1, 1>>>();

    // Fused QKV: Q-FFMA tiles overlap tc-KV tiles (complementary pipes)
    fused_qkv_kernel<<<3072, 256, TC_SMEM>>>(x, W_attn, b_attn);
    check_kv_kernel<<<(128 * 16 * 32 + 255) / 256, 256>>>(x, W_attn, b_attn);
    dim3 gkv(16, Mn / 128);
    guard_kv_kernel<<<gkv, 256>>>(x, W_attn, b_attn);

    rope_kernel<<<(BH * Tn * 32 + 255) / 256, 256>>>();
    bucket_kernel<<<BH * Tn / 128, 128>>>(R);
    sort_kernel<<<BH, 1024>>>();
    attn_kernel<<<BH * NCH, 128, ATTN_SMEM>>>();

    // Output projection: tcgen05 + verify + fallback
    dim3 go(8, Mn / 128);
    tc_proj_kernel<<<go, 256, TC_SMEM>>>(W_proj, b_proj, out);
    check_proj_kernel<<<(128 * 8 * 32 + 255) / 256, 256>>>(W_proj, b_proj, out);
    guard_proj_kernel<<<go, 256>>>(W_proj, b_proj, out);
}